// round 7
// baseline (speedup 1.0000x reference)
#include <cuda_runtime.h>
#include <cuda_bf16.h>

#define NDIM 128
#define EDIM 32
#define MAX_N 100000

// Scratch aggregation buffer: h = (1+eps)*x + scatter_sum(msg)
__device__ float g_h[(size_t)MAX_N * NDIM];

// ---------------- packed f32x2 helpers ----------------
__device__ __forceinline__ unsigned long long pack2(float x, float y) {
    unsigned long long r;
    asm("mov.b64 %0, {%1, %2};" : "=l"(r) : "f"(x), "f"(y));
    return r;
}
__device__ __forceinline__ void unpack2(unsigned long long v, float& x, float& y) {
    asm("mov.b64 {%0, %1}, %2;" : "=f"(x), "=f"(y) : "l"(v));
}
__device__ __forceinline__ void ffma2(unsigned long long& d, unsigned long long a, unsigned long long b) {
    asm("fma.rn.f32x2 %0, %1, %2, %0;" : "+l"(d) : "l"(a), "l"(b));
}

// ---------------- kernel 1: h = (1+eps) * x ----------------
__global__ void init_h_kernel(const float* __restrict__ x,
                              const float* __restrict__ eps, int n) {
    float s = 1.0f + __ldg(eps);
    int total4 = n * (NDIM / 4);
    const float4* x4 = (const float4*)x;
    float4* h4 = (float4*)g_h;
    for (int i = blockIdx.x * blockDim.x + threadIdx.x; i < total4;
         i += gridDim.x * blockDim.x) {
        float4 v = x4[i];
        v.x *= s; v.y *= s; v.z *= s; v.w *= s;
        h4[i] = v;
    }
}

// ---------------- kernel 2: edge MLP + gather + scatter ----------------
// msg[e] = edge_attr[e] @ We + be + x[j[e]];  red.add -> g_h[i[e]]
// 256 threads = 8 warps, 8 edges per warp -> 64 edges per block.
#define EPW 8
__global__ __launch_bounds__(256) void edge_kernel(
    const float* __restrict__ x,
    const int* __restrict__ ei,         // [2, E] int32: ei[e]=dst i, ei[nE+e]=src j
    const float* __restrict__ ea,       // [E, 32]
    const float* __restrict__ We,       // [32, 128]
    const float* __restrict__ be,       // [128]
    int nE, int nN)
{
    __shared__ float sWe[EDIM * NDIM];      // 16 KB
    __shared__ float sbe[NDIM];
    __shared__ float sea[8][EPW][EDIM];     // 8 KB

    int tid = threadIdx.x;
    for (int i = tid; i < EDIM * NDIM; i += blockDim.x) sWe[i] = We[i];
    if (tid < NDIM) sbe[tid] = be[tid];

    int warp = tid >> 5, lane = tid & 31;
    int ebase = blockIdx.x * (8 * EPW) + warp * EPW;

    // stage 8 edges' attrs: lane loads attr[lane] of each edge (coalesced 128B)
    #pragma unroll
    for (int nn = 0; nn < EPW; nn++) {
        int e = ebase + nn;
        sea[warp][nn][lane] = (e < nE) ? __ldg(&ea[(size_t)e * EDIM + lane]) : 0.0f;
    }
    // indices: lanes 0..7 load (i, j) of edge ebase+lane; clamp into [0,nN)
    int iv = 0, jv = 0;
    if (lane < EPW) {
        int e = ebase + lane;
        if (e < nE) {
            iv = min(max(__ldg(&ei[e]), 0), nN - 1);
            jv = min(max(__ldg(&ei[nE + e]), 0), nN - 1);
        }
    }
    __syncthreads();

    // register-blocked GEMM: lane owns cols [lane*4, lane*4+4)
    unsigned long long acc[EPW][2];
    #pragma unroll
    for (int nn = 0; nn < EPW; nn++) { acc[nn][0] = 0ULL; acc[nn][1] = 0ULL; }

    const float4* We4 = (const float4*)sWe;
    #pragma unroll
    for (int d = 0; d < EDIM; d++) {
        float4 w = We4[d * 32 + lane];
        unsigned long long w01 = pack2(w.x, w.y);
        unsigned long long w23 = pack2(w.z, w.w);
        #pragma unroll
        for (int nn = 0; nn < EPW; nn++) {
            float a = sea[warp][nn][d];
            unsigned long long aa = pack2(a, a);
            ffma2(acc[nn][0], aa, w01);
            ffma2(acc[nn][1], aa, w23);
        }
    }

    float4 b = ((const float4*)sbe)[lane];
    #pragma unroll
    for (int nn = 0; nn < EPW; nn++) {
        int e = ebase + nn;
        if (e < nE) {
            int jn  = __shfl_sync(0xffffffffu, jv, nn);
            int in_ = __shfl_sync(0xffffffffu, iv, nn);
            float4 xv = __ldg(&((const float4*)x)[(size_t)jn * 32 + lane]);
            float m0, m1, m2, m3;
            unpack2(acc[nn][0], m0, m1);
            unpack2(acc[nn][1], m2, m3);
            m0 += b.x + xv.x;
            m1 += b.y + xv.y;
            m2 += b.z + xv.z;
            m3 += b.w + xv.w;
            float* dst = g_h + (size_t)in_ * NDIM + lane * 4;
            asm volatile("red.global.add.v4.f32 [%0], {%1,%2,%3,%4};"
                         :: "l"(dst), "f"(m0), "f"(m1), "f"(m2), "f"(m3)
                         : "memory");
        }
    }
}

// ---------------- kernel 3: node MLP + LayerNorm ----------------
// out = LN(relu(h@W1+b1)@W2+b2)
// 512 threads = 16 warps, 8 nodes/warp -> 128 nodes/block.
// smem: W1 (64KB) + W2 (64KB) + per-warp 8x128 staging (64KB) = 192KB
#define NPW 8
__global__ __launch_bounds__(512) void node_kernel(
    const float* __restrict__ W1, const float* __restrict__ b1,
    const float* __restrict__ W2, const float* __restrict__ b2,
    const float* __restrict__ gamma, const float* __restrict__ beta,
    float* __restrict__ out, int n)
{
    extern __shared__ float sm[];
    float* sW1 = sm;                       // 16384 floats
    float* sW2 = sm + NDIM * NDIM;         // 16384 floats
    float* sstage = sm + 2 * NDIM * NDIM;  // 16 warps * 8 * 128 floats

    int tid = threadIdx.x, warp = tid >> 5, lane = tid & 31;
    for (int i = tid; i < NDIM * NDIM; i += blockDim.x) {
        sW1[i] = W1[i];
        sW2[i] = W2[i];
    }
    __syncthreads();

    float* st = sstage + warp * (NPW * NDIM);
    int nbase = blockIdx.x * (16 * NPW) + warp * NPW;

    // stage h rows (coalesced float4 per node)
    #pragma unroll
    for (int nn = 0; nn < NPW; nn++) {
        int node = nbase + nn;
        float4 v = make_float4(0.f, 0.f, 0.f, 0.f);
        if (node < n) v = ((const float4*)g_h)[(size_t)node * 32 + lane];
        ((float4*)st)[nn * 32 + lane] = v;
    }
    __syncwarp();

    // ---- layer 1: t = relu(h @ W1 + b1) ----
    unsigned long long acc[NPW][2];
    #pragma unroll
    for (int nn = 0; nn < NPW; nn++) { acc[nn][0] = 0ULL; acc[nn][1] = 0ULL; }

    const float4* W14 = (const float4*)sW1;
    #pragma unroll 4
    for (int d = 0; d < NDIM; d++) {
        float4 w = W14[d * 32 + lane];
        unsigned long long w01 = pack2(w.x, w.y);
        unsigned long long w23 = pack2(w.z, w.w);
        #pragma unroll
        for (int nn = 0; nn < NPW; nn++) {
            float hv = st[nn * NDIM + d];
            unsigned long long aa = pack2(hv, hv);
            ffma2(acc[nn][0], aa, w01);
            ffma2(acc[nn][1], aa, w23);
        }
    }

    float4 b1v = __ldg(&((const float4*)b1)[lane]);
    __syncwarp();  // all lanes done reading st before overwrite
    #pragma unroll
    for (int nn = 0; nn < NPW; nn++) {
        float t0, t1, t2, t3;
        unpack2(acc[nn][0], t0, t1);
        unpack2(acc[nn][1], t2, t3);
        t0 = fmaxf(t0 + b1v.x, 0.f);
        t1 = fmaxf(t1 + b1v.y, 0.f);
        t2 = fmaxf(t2 + b1v.z, 0.f);
        t3 = fmaxf(t3 + b1v.w, 0.f);
        ((float4*)st)[nn * 32 + lane] = make_float4(t0, t1, t2, t3);
    }
    __syncwarp();

    // ---- layer 2: o = t @ W2 + b2 ----
    #pragma unroll
    for (int nn = 0; nn < NPW; nn++) { acc[nn][0] = 0ULL; acc[nn][1] = 0ULL; }
    const float4* W24 = (const float4*)sW2;
    #pragma unroll 4
    for (int d = 0; d < NDIM; d++) {
        float4 w = W24[d * 32 + lane];
        unsigned long long w01 = pack2(w.x, w.y);
        unsigned long long w23 = pack2(w.z, w.w);
        #pragma unroll
        for (int nn = 0; nn < NPW; nn++) {
            float tv = st[nn * NDIM + d];
            unsigned long long aa = pack2(tv, tv);
            ffma2(acc[nn][0], aa, w01);
            ffma2(acc[nn][1], aa, w23);
        }
    }

    float4 b2v = __ldg(&((const float4*)b2)[lane]);
    float4 gv = __ldg(&((const float4*)gamma)[lane]);
    float4 bv = __ldg(&((const float4*)beta)[lane]);

    // ---- LayerNorm per node ----
    #pragma unroll
    for (int nn = 0; nn < NPW; nn++) {
        int node = nbase + nn;
        float o0, o1, o2, o3;
        unpack2(acc[nn][0], o0, o1);
        unpack2(acc[nn][1], o2, o3);
        o0 += b2v.x; o1 += b2v.y; o2 += b2v.z; o3 += b2v.w;
        float s = o0 + o1 + o2 + o3;
        float s2 = o0 * o0 + o1 * o1 + o2 * o2 + o3 * o3;
        #pragma unroll
        for (int off = 16; off > 0; off >>= 1) {
            s  += __shfl_xor_sync(0xffffffffu, s, off);
            s2 += __shfl_xor_sync(0xffffffffu, s2, off);
        }
        float mean = s * (1.0f / NDIM);
        float var = s2 * (1.0f / NDIM) - mean * mean;
        float rstd = rsqrtf(var + 1e-5f);
        float4 o;
        o.x = (o0 - mean) * rstd * gv.x + bv.x;
        o.y = (o1 - mean) * rstd * gv.y + bv.y;
        o.z = (o2 - mean) * rstd * gv.z + bv.z;
        o.w = (o3 - mean) * rstd * gv.w + bv.w;
        if (node < n) ((float4*)out)[(size_t)node * 32 + lane] = o;
    }
}

// ---------------- launch ----------------
extern "C" void kernel_launch(void* const* d_in, const int* in_sizes, int n_in,
                              void* d_out, int out_size) {
    const float* x      = (const float*)d_in[0];
    const int*   ei     = (const int*)d_in[1];     // int32 (harness normalizes int64)
    const float* ea     = (const float*)d_in[2];
    const float* be     = (const float*)d_in[4];
    const float* We     = (const float*)d_in[3];
    const float* W1     = (const float*)d_in[5];
    const float* b1     = (const float*)d_in[6];
    const float* W2     = (const float*)d_in[7];
    const float* b2     = (const float*)d_in[8];
    const float* eps    = (const float*)d_in[9];
    const float* gamma  = (const float*)d_in[10];
    const float* beta   = (const float*)d_in[11];
    float* out = (float*)d_out;

    int n = in_sizes[0] / NDIM;        // 100000
    int nE = in_sizes[2] / EDIM;       // 600000

    // kernel 1: init h = (1+eps)*x
    {
        int total4 = n * (NDIM / 4);
        int blocks = (total4 + 255) / 256;
        if (blocks > 4096) blocks = 4096;
        init_h_kernel<<<blocks, 256>>>(x, eps, n);
    }
    // kernel 2: edges
    {
        int edges_per_block = 8 * EPW;  // 64
        int blocks = (nE + edges_per_block - 1) / edges_per_block;
        edge_kernel<<<blocks, 256>>>(x, ei, ea, We, be, nE, n);
    }
    // kernel 3: node MLP + LN
    {
        int smem = (2 * NDIM * NDIM + 16 * NPW * NDIM) * sizeof(float); // 192KB
        cudaFuncSetAttribute(node_kernel,
                             cudaFuncAttributeMaxDynamicSharedMemorySize, smem);
        int nodes_per_block = 16 * NPW; // 128
        int blocks = (n + nodes_per_block - 1) / nodes_per_block;
        node_kernel<<<blocks, 512, smem>>>(W1, b1, W2, b2, gamma, beta, out, n);
    }
}